// round 5
// baseline (speedup 1.0000x reference)
#include <cuda_runtime.h>

#define BB 256
#define TT 256
#define CC 1024
#define LL 64
#define SS 129          // 2L+1
#define GW 68           // padded gather width: 64 labels + 1 blank
#define NEGV (-1e30f)
#define EPSF 1e-7f
#define LN2F 0.69314718055994530942f

// scratch (no allocation allowed -> __device__ global)
__device__ float g_buf[(size_t)BB * TT * GW];   // emit table, LOG2 domain

__device__ __forceinline__ float fexp2(float x) {
    float y; asm("ex2.approx.ftz.f32 %0, %1;" : "=f"(y) : "f"(x)); return y;
}
__device__ __forceinline__ float flog2(float x) {
    float y; asm("lg2.approx.ftz.f32 %0, %1;" : "=f"(y) : "f"(x)); return y;
}

// int64-vs-int32 label dtype detection, one load + ballot per warp.
__device__ __forceinline__ bool detect_i64(const int* yt, int lane) {
    return __all_sync(0xffffffffu, yt[2 * lane + 1] == 0);
}
__device__ __forceinline__ int load_lab(const int* yt, bool is64, int idx) {
    int v = is64 ? yt[2 * idx] : yt[idx];
    return min(max(v, 0), CC - 1);              // clamp: safety net
}

// ---------------------------------------------------------------------------
// Kernel 1: per (b,t) row.  log_softmax(log(y+EPS)) = log(y+EPS)-log(sum(y+EPS))
// -> one plain sum over C.  One warp per row; gather the 65 reachable classes.
// y_pred is read with __ldcs (evict-first) so the 256MB stream does NOT evict
// the 17.8MB g_buf working set from L2 -> k_alpha refills become L2 hits.
// ---------------------------------------------------------------------------
__global__ void k_reduce_gather(const float* __restrict__ yp,
                                const int*   __restrict__ yt) {
    int warp = (blockIdx.x * blockDim.x + threadIdx.x) >> 5;
    int lane = threadIdx.x & 31;
    if (warp >= BB * TT) return;
    int b = warp >> 8;                          // row-major (B,T,C)

    bool is64 = detect_i64(yt, lane);

    const float*  row  = yp + (size_t)warp * CC;
    const float4* row4 = (const float4*)row;

    float s = 0.f;
    #pragma unroll
    for (int k = 0; k < 8; ++k) {               // 8 coalesced float4 per lane
        float4 v = __ldcs(row4 + lane + 32 * k);    // streaming: evict-first
        s += (v.x + v.y) + (v.z + v.w);
    }
    #pragma unroll
    for (int o = 16; o; o >>= 1) s += __shfl_xor_sync(0xffffffffu, s, o);

    float l2Z = flog2(s + (float)CC * EPSF);    // log2(sum(y+EPS))

    float* go = g_buf + (size_t)warp * GW;
    #pragma unroll
    for (int r = 0; r < 2; ++r) {
        int j   = lane + 32 * r;
        int lab = load_lab(yt, is64, b * LL + j);
        go[j]   = flog2(row[lab] + EPSF) - l2Z;      // L1 hit: row just read
    }
    if (lane == 0)
        go[64] = flog2(row[CC - 1] + EPSF) - l2Z;    // blank
}

// ---------------------------------------------------------------------------
// Kernel 2: alpha recursion, LOG2 domain.  One warp per batch, 5 states per
// thread, 2 shuffles per step, emit prefetch ring depth 5 (covers L2 latency).
// lse3 trick: one exp arg is always 0 -> t = 1 + 2^u + 2^v (2 MUFU + 1 log).
// ---------------------------------------------------------------------------
__device__ __forceinline__ float stepf(float a1, float a2, float a3, float e) {
    float mm = fmaxf(a1, a2);
    float mx = fmaxf(mm, a3);
    float u  = fminf(a1, a2) - mx;
    float v  = fminf(mm, a3) - mx;
    float t  = 1.0f + fexp2(u) + fexp2(v);
    return mx + flog2(t) + e;
}

__global__ void __launch_bounds__(128, 1)
k_alpha(const int* __restrict__ yt, float* __restrict__ out) {
    int b    = (blockIdx.x * blockDim.x + threadIdx.x) >> 5;
    int lane = threadIdx.x & 31;
    if (b >= BB) return;

    bool is64 = detect_i64(yt, lane);

    int  eidx[5];
    bool valid[5], skip[5];
    #pragma unroll
    for (int i = 0; i < 5; ++i) {
        int s    = 5 * lane + i;
        valid[i] = (s < SS);
        bool odd = (s & 1);
        eidx[i]  = odd ? ((s - 1) >> 1) : 64;
        skip[i]  = false;
        if (valid[i] && odd && s >= 3) {        // pos>=2 and label state
            int j = (s - 1) >> 1;               // j >= 1 here
            skip[i] = (load_lab(yt, is64, b * LL + j) !=
                       load_lab(yt, is64, b * LL + j - 1));
        }
    }

    const float* gb = g_buf + (size_t)b * TT * GW;

    // t = 0 init: only states 0,1 live
    float a[5];
    #pragma unroll
    for (int i = 0; i < 5; ++i) {
        int s = 5 * lane + i;
        a[i]  = (s < 2) ? gb[eidx[i]] : NEGV;
    }

    // emit prefetch ring, depth 5 (t+1 .. t+5)
    float eb[5][5];
    #pragma unroll
    for (int d = 0; d < 5; ++d) {
        const float* gt = gb + (size_t)(1 + d) * GW;
        #pragma unroll
        for (int i = 0; i < 5; ++i) eb[d][i] = valid[i] ? gt[eidx[i]] : NEGV;
    }

    // (TT-1) = 255 steps = 51 chunks of 5; ring slots are compile-time
    for (int t = 1; t < TT; t += 5) {
        #pragma unroll
        for (int d = 0; d < 5; ++d) {
            int tc = t + d;
            float ec[5];
            #pragma unroll
            for (int i = 0; i < 5; ++i) ec[i] = eb[d][i];
            if (tc + 5 < TT) {                  // refill this slot from 5 ahead
                const float* gn = gb + (size_t)(tc + 5) * GW;
                #pragma unroll
                for (int i = 0; i < 5; ++i) eb[d][i] = valid[i] ? gn[eidx[i]] : NEGV;
            }

            float p4 = __shfl_up_sync(0xffffffffu, a[4], 1);   // state 5*lane-1
            float p3 = __shfl_up_sync(0xffffffffu, a[3], 1);   // state 5*lane-2
            if (lane == 0) { p4 = NEGV; p3 = NEGV; }

            float n0 = stepf(a[0], p4,   skip[0] ? p3   : NEGV, ec[0]);
            float n1 = stepf(a[1], a[0], skip[1] ? p4   : NEGV, ec[1]);
            float n2 = stepf(a[2], a[1], skip[2] ? a[0] : NEGV, ec[2]);
            float n3 = stepf(a[3], a[2], skip[3] ? a[1] : NEGV, ec[3]);
            float n4 = stepf(a[4], a[3], skip[4] ? a[2] : NEGV, ec[4]);
            a[0] = n0; a[1] = n1; a[2] = n2; a[3] = n3; a[4] = n4;
        }
    }

    // states 127 (i=2) and 128 (i=3) live in lane 25; convert log2 -> ln
    if (lane == 25) {
        float x = a[2], y = a[3];
        float m = fmaxf(x, y);
        float r = m + flog2(1.0f + fexp2(fminf(x, y) - m));
        out[b] = -r * LN2F;
    }
}

// ---------------------------------------------------------------------------
extern "C" void kernel_launch(void* const* d_in, const int* in_sizes, int n_in,
                              void* d_out, int out_size) {
    // y_pred is by far the larger buffer; robust to metadata ordering.
    const float* yp;
    const int*   yt;
    if (in_sizes[0] > in_sizes[1]) {
        yp = (const float*)d_in[0];
        yt = (const int*)d_in[1];
    } else {
        yp = (const float*)d_in[1];
        yt = (const int*)d_in[0];
    }
    float* out = (float*)d_out;

    k_reduce_gather<<<(BB * TT) / 8, 256>>>(yp, yt);   // one warp per (b,t) row
    k_alpha<<<BB / 4, 128>>>(yt, out);                 // one warp per batch
}

// round 7
// speedup vs baseline: 1.5319x; 1.5319x over previous
#include <cuda_runtime.h>
#include <cstdint>

#define BB 256
#define TT 256
#define CC 1024
#define LL 64
#define SS 129          // 2L+1
#define GW 72           // padded gather width: 64 labels + blank@64, pad to 72
#define CH 16           // time-rows per smem chunk
#define NEGV (-1e30f)
#define EPSF 1e-7f
#define LN2F 0.69314718055994530942f

// scratch (no allocation allowed -> __device__ global)
__device__ float g_buf[(size_t)BB * TT * GW];   // emit table, LOG2 domain

__device__ __forceinline__ float fexp2(float x) {
    float y; asm("ex2.approx.ftz.f32 %0, %1;" : "=f"(y) : "f"(x)); return y;
}
__device__ __forceinline__ float flog2(float x) {
    float y; asm("lg2.approx.ftz.f32 %0, %1;" : "=f"(y) : "f"(x)); return y;
}

// int64-vs-int32 label dtype detection, one load + ballot per warp.
__device__ __forceinline__ bool detect_i64(const int* yt, int lane) {
    return __all_sync(0xffffffffu, yt[2 * lane + 1] == 0);
}
__device__ __forceinline__ int load_lab(const int* yt, bool is64, int idx) {
    int v = is64 ? yt[2 * idx] : yt[idx];
    return min(max(v, 0), CC - 1);              // clamp: safety net
}

// ---------------------------------------------------------------------------
// Kernel 1: per (b,t) row.  log_softmax(log(y+EPS)) = log(y+EPS)-log(sum(y+EPS))
// -> one plain sum over C.  One warp per row; gather the 65 reachable classes.
// ---------------------------------------------------------------------------
__global__ void k_reduce_gather(const float* __restrict__ yp,
                                const int*   __restrict__ yt) {
    int warp = (blockIdx.x * blockDim.x + threadIdx.x) >> 5;
    int lane = threadIdx.x & 31;
    if (warp >= BB * TT) return;
    int b = warp >> 8;                          // row-major (B,T,C)

    bool is64 = detect_i64(yt, lane);

    const float*  row  = yp + (size_t)warp * CC;
    const float4* row4 = (const float4*)row;

    float s = 0.f;
    #pragma unroll
    for (int k = 0; k < 8; ++k) {               // 8 coalesced float4 per lane
        float4 v = row4[lane + 32 * k];
        s += (v.x + v.y) + (v.z + v.w);
    }
    #pragma unroll
    for (int o = 16; o; o >>= 1) s += __shfl_xor_sync(0xffffffffu, s, o);

    float l2Z = flog2(s + (float)CC * EPSF);    // log2(sum(y+EPS))

    float* go = g_buf + (size_t)warp * GW;
    #pragma unroll
    for (int r = 0; r < 2; ++r) {
        int j   = lane + 32 * r;
        int lab = load_lab(yt, is64, b * LL + j);
        go[j]   = flog2(row[lab] + EPSF) - l2Z;      // L1 hit: row just read
    }
    if (lane == 0)
        go[64] = flog2(row[CC - 1] + EPSF) - l2Z;    // blank
}

// ---------------------------------------------------------------------------
// Kernel 2: alpha recursion, LOG2 domain.  One warp per batch, 5 states per
// thread, 2 shuffles per step.  Emit rows staged to smem in CH-row chunks via
// cp.async (double-buffered): gather loads become LDS, DRAM latency is covered
// by a whole chunk of compute.
// ---------------------------------------------------------------------------
__device__ __forceinline__ float stepf(float a1, float a2, float a3, float e) {
    float mm = fmaxf(a1, a2);
    float mx = fmaxf(mm, a3);
    float u  = fminf(a1, a2) - mx;
    float v  = fminf(mm, a3) - mx;
    float t  = 1.0f + fexp2(u) + fexp2(v);
    return mx + flog2(t) + e;
}

// stage CH rows (CH*GW floats = 9 float4 per lane) global -> shared, async
__device__ __forceinline__ void issue_chunk(const float4* gsrc,
                                            unsigned int sdst, int lane) {
    #pragma unroll
    for (int k = 0; k < (CH * GW) / (4 * 32); ++k) {   // 9 iters
        int i4 = lane + 32 * k;
        asm volatile("cp.async.ca.shared.global [%0], [%1], 16;\n"
                     :: "r"(sdst + 16u * i4), "l"(gsrc + i4));
    }
    asm volatile("cp.async.commit_group;\n" ::: "memory");
}
__device__ __forceinline__ void wait_chunk() {
    asm volatile("cp.async.wait_group 0;\n" ::: "memory");
    __syncwarp();
}

__global__ void __launch_bounds__(128, 1)
k_alpha(const int* __restrict__ yt, float* __restrict__ out) {
    __shared__ __align__(16) float sm[4][2][CH * GW];  // 36,864 B

    int w    = threadIdx.x >> 5;
    int b    = blockIdx.x * 4 + w;
    int lane = threadIdx.x & 31;
    if (b >= BB) return;

    bool is64 = detect_i64(yt, lane);

    int  eidx[5];
    bool valid[5], skip[5];
    #pragma unroll
    for (int i = 0; i < 5; ++i) {
        int s    = 5 * lane + i;
        valid[i] = (s < SS);
        bool odd = (s & 1);
        eidx[i]  = odd ? ((s - 1) >> 1) : 64;
        skip[i]  = false;
        if (valid[i] && odd && s >= 3) {        // pos>=2 and label state
            int j = (s - 1) >> 1;               // j >= 1 here
            skip[i] = (load_lab(yt, is64, b * LL + j) !=
                       load_lab(yt, is64, b * LL + j - 1));
        }
    }

    const float4* gb4 = (const float4*)(g_buf + (size_t)b * TT * GW);
    unsigned int sbase[2] = {
        (unsigned int)__cvta_generic_to_shared(&sm[w][0][0]),
        (unsigned int)__cvta_generic_to_shared(&sm[w][1][0])
    };

    // preload chunk 0 (rows 0..15)
    issue_chunk(gb4, sbase[0], lane);
    wait_chunk();

    float a[5];
    {   // t = 0 init from smem row 0: only states 0,1 live
        const float* s0 = &sm[w][0][0];
        #pragma unroll
        for (int i = 0; i < 5; ++i) {
            int s = 5 * lane + i;
            a[i]  = (s < 2) ? s0[eidx[i]] : NEGV;
        }
    }

    #pragma unroll 1
    for (int c = 0; c < TT / CH; ++c) {
        if (c + 1 < TT / CH)                    // stream next chunk while computing
            issue_chunk(gb4 + (size_t)(c + 1) * (CH * GW / 4),
                        sbase[(c + 1) & 1], lane);

        const float* sbuf = &sm[w][c & 1][0];
        int r0 = (c == 0) ? 1 : 0;              // t=0 consumed by init

        #pragma unroll
        for (int r = 0; r < CH; ++r) {
            if (r < r0) continue;
            const float* srow = sbuf + r * GW;
            float ec[5];
            #pragma unroll
            for (int i = 0; i < 5; ++i) ec[i] = valid[i] ? srow[eidx[i]] : NEGV;

            float p4 = __shfl_up_sync(0xffffffffu, a[4], 1);   // state 5*lane-1
            float p3 = __shfl_up_sync(0xffffffffu, a[3], 1);   // state 5*lane-2
            if (lane == 0) { p4 = NEGV; p3 = NEGV; }

            float n0 = stepf(a[0], p4,   skip[0] ? p3   : NEGV, ec[0]);
            float n1 = stepf(a[1], a[0], skip[1] ? p4   : NEGV, ec[1]);
            float n2 = stepf(a[2], a[1], skip[2] ? a[0] : NEGV, ec[2]);
            float n3 = stepf(a[3], a[2], skip[3] ? a[1] : NEGV, ec[3]);
            float n4 = stepf(a[4], a[3], skip[4] ? a[2] : NEGV, ec[4]);
            a[0] = n0; a[1] = n1; a[2] = n2; a[3] = n3; a[4] = n4;
        }

        if (c + 1 < TT / CH) wait_chunk();      // next buffer ready
    }

    // states 127 (i=2) and 128 (i=3) live in lane 25; convert log2 -> ln
    if (lane == 25) {
        float x = a[2], y = a[3];
        float m = fmaxf(x, y);
        float r = m + flog2(1.0f + fexp2(fminf(x, y) - m));
        out[b] = -r * LN2F;
    }
}

// ---------------------------------------------------------------------------
extern "C" void kernel_launch(void* const* d_in, const int* in_sizes, int n_in,
                              void* d_out, int out_size) {
    // y_pred is by far the larger buffer; robust to metadata ordering.
    const float* yp;
    const int*   yt;
    if (in_sizes[0] > in_sizes[1]) {
        yp = (const float*)d_in[0];
        yt = (const int*)d_in[1];
    } else {
        yp = (const float*)d_in[1];
        yt = (const int*)d_in[0];
    }
    float* out = (float*)d_out;

    k_reduce_gather<<<(BB * TT) / 8, 256>>>(yp, yt);   // one warp per (b,t) row
    k_alpha<<<BB / 4, 128>>>(yt, out);                 // one warp per batch
}